// round 1
// baseline (speedup 1.0000x reference)
#include <cuda_runtime.h>
#include <math.h>

#define T_ 1024
#define C_ 1024
#define B_ 4
#define H_ 16
#define L_ 12
#define V_ 50304
#define M_ 4096   // B*T tokens

// ---------------- scratch (static device globals: the allowed workaround) ---
__device__ float g_x[(size_t)M_ * C_];          // residual stream (16 MB)
__device__ float g_h[(size_t)M_ * C_];          // LN output       (16 MB)
__device__ float g_big[(size_t)M_ * 4 * C_];    // qkv+att alias / mlp (64 MB)
__device__ float g_logits[(size_t)M_ * V_];     // fallback logits (824 MB)

// ---------------- embedding ----------------
__global__ __launch_bounds__(256) void embed_kernel(
    const int* __restrict__ idx, const float* __restrict__ tok,
    const float* __restrict__ pos, float* __restrict__ x)
{
    int bt = blockIdx.x;
    int t = bt & (T_ - 1);
    int token = idx[bt];
    int c = threadIdx.x * 4;
    float4 tv = *(const float4*)(tok + (size_t)token * C_ + c);
    float4 pv = *(const float4*)(pos + (size_t)t * C_ + c);
    *(float4*)(x + (size_t)bt * C_ + c) =
        make_float4(tv.x + pv.x, tv.y + pv.y, tv.z + pv.z, tv.w + pv.w);
}

// ---------------- layernorm (one block per row, C=1024) ----------------
__global__ __launch_bounds__(256) void ln_kernel(
    const float* __restrict__ x, const float* __restrict__ g,
    const float* __restrict__ b, float* __restrict__ y)
{
    __shared__ float red[8];
    __shared__ float bc_mean, bc_inv;
    int row = blockIdx.x, tid = threadIdx.x;
    const float* xr = x + (size_t)row * C_;
    float4 xv = *(const float4*)(xr + tid * 4);
    float s = xv.x + xv.y + xv.z + xv.w;
    #pragma unroll
    for (int o = 16; o; o >>= 1) s += __shfl_xor_sync(0xffffffffu, s, o);
    if ((tid & 31) == 0) red[tid >> 5] = s;
    __syncthreads();
    if (tid == 0) {
        float t = 0.f;
        #pragma unroll
        for (int i = 0; i < 8; i++) t += red[i];
        bc_mean = t * (1.0f / C_);
    }
    __syncthreads();
    float mean = bc_mean;
    float d0 = xv.x - mean, d1 = xv.y - mean, d2 = xv.z - mean, d3 = xv.w - mean;
    float sq = d0 * d0 + d1 * d1 + d2 * d2 + d3 * d3;
    #pragma unroll
    for (int o = 16; o; o >>= 1) sq += __shfl_xor_sync(0xffffffffu, sq, o);
    if ((tid & 31) == 0) red[tid >> 5] = sq;
    __syncthreads();
    if (tid == 0) {
        float t = 0.f;
        #pragma unroll
        for (int i = 0; i < 8; i++) t += red[i];
        bc_inv = rsqrtf(t * (1.0f / C_) + 1e-5f);
    }
    __syncthreads();
    float inv = bc_inv;
    float4 gv = *(const float4*)(g + tid * 4);
    float4 bv = *(const float4*)(b + tid * 4);
    *(float4*)(y + (size_t)row * C_ + tid * 4) =
        make_float4(d0 * inv * gv.x + bv.x, d1 * inv * gv.y + bv.y,
                    d2 * inv * gv.z + bv.z, d3 * inv * gv.w + bv.w);
}

// ---------------- SGEMM: C = A(MxK) @ B(KxN) [+bias][+resid][relu] -------
// 128x128 tile, BK=8, 256 threads, 8x8 per-thread microtile.
template <int BIAS, int RELU, int RESID>
__global__ __launch_bounds__(256) void sgemm_kernel(
    const float* __restrict__ A, const float* __restrict__ B,
    const float* __restrict__ bias, const float* __restrict__ resid,
    float* __restrict__ C, int M, int N, int K)
{
    __shared__ float As[8][132];
    __shared__ float Bs[8][132];
    int tid = threadIdx.x;
    int bx = blockIdx.x, by = blockIdx.y;
    int tx = tid & 15, ty = tid >> 4;

    float acc[8][8];
    #pragma unroll
    for (int i = 0; i < 8; i++)
        #pragma unroll
        for (int j = 0; j < 8; j++) acc[i][j] = 0.f;

    int arow = tid >> 1, acol = (tid & 1) * 4;
    int brow = tid >> 5, bcol = (tid & 31) * 4;
    const float* Ag = A + (size_t)(by * 128 + arow) * K + acol;
    const float* Bg = B + (size_t)brow * N + (size_t)bx * 128 + bcol;

    for (int k0 = 0; k0 < K; k0 += 8) {
        float4 av = *(const float4*)(Ag + k0);
        float4 bv = *(const float4*)(Bg + (size_t)k0 * N);
        As[acol + 0][arow] = av.x;
        As[acol + 1][arow] = av.y;
        As[acol + 2][arow] = av.z;
        As[acol + 3][arow] = av.w;
        *(float4*)&Bs[brow][bcol] = bv;
        __syncthreads();
        #pragma unroll
        for (int kk = 0; kk < 8; kk++) {
            float4 a0 = *(const float4*)&As[kk][ty * 8];
            float4 a1 = *(const float4*)&As[kk][ty * 8 + 4];
            float4 b0 = *(const float4*)&Bs[kk][tx * 8];
            float4 b1 = *(const float4*)&Bs[kk][tx * 8 + 4];
            float ar[8] = {a0.x, a0.y, a0.z, a0.w, a1.x, a1.y, a1.z, a1.w};
            float br[8] = {b0.x, b0.y, b0.z, b0.w, b1.x, b1.y, b1.z, b1.w};
            #pragma unroll
            for (int i = 0; i < 8; i++)
                #pragma unroll
                for (int j = 0; j < 8; j++) acc[i][j] += ar[i] * br[j];
        }
        __syncthreads();
    }

    float bfrag[8];
    if (BIAS) {
        float4 q0 = *(const float4*)(bias + (size_t)bx * 128 + tx * 8);
        float4 q1 = *(const float4*)(bias + (size_t)bx * 128 + tx * 8 + 4);
        bfrag[0] = q0.x; bfrag[1] = q0.y; bfrag[2] = q0.z; bfrag[3] = q0.w;
        bfrag[4] = q1.x; bfrag[5] = q1.y; bfrag[6] = q1.z; bfrag[7] = q1.w;
    }
    #pragma unroll
    for (int i = 0; i < 8; i++) {
        size_t off = (size_t)(by * 128 + ty * 8 + i) * N + (size_t)bx * 128 + tx * 8;
        float o0[8];
        #pragma unroll
        for (int j = 0; j < 8; j++) {
            float vv = acc[i][j];
            if (BIAS) vv += bfrag[j];
            if (RESID) vv += resid[off + j];
            if (RELU) vv = fmaxf(vv, 0.f);
            o0[j] = vv;
        }
        *(float4*)(C + off) = make_float4(o0[0], o0[1], o0[2], o0[3]);
        *(float4*)(C + off + 4) = make_float4(o0[4], o0[5], o0[6], o0[7]);
    }
}

// ---------------- causal flash attention (HS=64, 64-query tile) ----------
// grid: (T/64, B*H), block 256. Thread t -> row = t>>2, seg = t&3 (16 cols).
#define ATTN_SMEM (4 * 64 * 68 * 4)
__global__ __launch_bounds__(256) void attn_kernel(
    const float* __restrict__ Q, const float* __restrict__ K,
    const float* __restrict__ V, float* __restrict__ O)
{
    extern __shared__ float sm[];
    float (*Qs)[68]  = (float(*)[68])sm;                 // [q][d]
    float (*KsT)[68] = (float(*)[68])(sm + 64 * 68);     // [d][k]  (transposed)
    float (*Vs)[68]  = (float(*)[68])(sm + 2 * 64 * 68); // [k][d]
    float (*Ps)[68]  = (float(*)[68])(sm + 3 * 64 * 68); // [q][k]

    int qb = blockIdx.x;
    int bh = blockIdx.y;
    int b = bh >> 4, hh = bh & 15;
    size_t base = (size_t)b * T_ * C_ + (size_t)hh * 64;
    int tid = threadIdx.x;
    int row = tid >> 2, seg = tid & 3;
    int gq = qb * 64 + row;

    for (int i = tid; i < 64 * 16; i += 256) {
        int r = i >> 4, c4 = (i & 15) << 2;
        *(float4*)&Qs[r][c4] = *(const float4*)&Q[base + (size_t)(qb * 64 + r) * C_ + c4];
    }
    __syncthreads();

    float m = -1e30f, l = 0.f;
    float o[16];
    #pragma unroll
    for (int j = 0; j < 16; j++) o[j] = 0.f;

    for (int kb = 0; kb <= qb; kb++) {
        for (int i = tid; i < 64 * 16; i += 256) {
            int r = i >> 4, c4 = (i & 15) << 2;
            size_t goff = base + (size_t)(kb * 64 + r) * C_ + c4;
            float4 kv = *(const float4*)&K[goff];
            KsT[c4 + 0][r] = kv.x;
            KsT[c4 + 1][r] = kv.y;
            KsT[c4 + 2][r] = kv.z;
            KsT[c4 + 3][r] = kv.w;
            *(float4*)&Vs[r][c4] = *(const float4*)&V[goff];
        }
        __syncthreads();

        // S = Q K^T for this thread's 16 contiguous key-cols [seg*16 .. )
        float sv[16];
        #pragma unroll
        for (int j = 0; j < 16; j++) sv[j] = 0.f;
        #pragma unroll 16
        for (int d = 0; d < 64; d++) {
            float qd = Qs[row][d];
            float4 k0 = *(const float4*)&KsT[d][seg * 16];
            float4 k1 = *(const float4*)&KsT[d][seg * 16 + 4];
            float4 k2 = *(const float4*)&KsT[d][seg * 16 + 8];
            float4 k3 = *(const float4*)&KsT[d][seg * 16 + 12];
            sv[0]  += qd * k0.x; sv[1]  += qd * k0.y; sv[2]  += qd * k0.z; sv[3]  += qd * k0.w;
            sv[4]  += qd * k1.x; sv[5]  += qd * k1.y; sv[6]  += qd * k1.z; sv[7]  += qd * k1.w;
            sv[8]  += qd * k2.x; sv[9]  += qd * k2.y; sv[10] += qd * k2.z; sv[11] += qd * k2.w;
            sv[12] += qd * k3.x; sv[13] += qd * k3.y; sv[14] += qd * k3.z; sv[15] += qd * k3.w;
        }
        #pragma unroll
        for (int j = 0; j < 16; j++) {
            int gk = kb * 64 + seg * 16 + j;
            sv[j] = (gk <= gq) ? sv[j] * 0.125f : -1e30f;
        }

        // online softmax: reduce over the 4 lanes sharing this row
        float tmax = sv[0];
        #pragma unroll
        for (int j = 1; j < 16; j++) tmax = fmaxf(tmax, sv[j]);
        tmax = fmaxf(tmax, __shfl_xor_sync(0xffffffffu, tmax, 1));
        tmax = fmaxf(tmax, __shfl_xor_sync(0xffffffffu, tmax, 2));
        float mnew = fmaxf(m, tmax);
        float corr = __expf(m - mnew);
        float ls = 0.f;
        #pragma unroll
        for (int j = 0; j < 16; j++) {
            float p = __expf(sv[j] - mnew);
            Ps[row][seg * 16 + j] = p;
            ls += p;
        }
        ls += __shfl_xor_sync(0xffffffffu, ls, 1);
        ls += __shfl_xor_sync(0xffffffffu, ls, 2);
        l = l * corr + ls;
        m = mnew;
        #pragma unroll
        for (int j = 0; j < 16; j++) o[j] *= corr;
        __syncwarp();

        // O += P @ V  (this thread's 16 output dims [seg*16 .. ))
        #pragma unroll 8
        for (int kk = 0; kk < 64; kk++) {
            float p = Ps[row][kk];
            const float* vr = &Vs[kk][seg * 16];
            float4 v0 = *(const float4*)(vr);
            float4 v1 = *(const float4*)(vr + 4);
            float4 v2 = *(const float4*)(vr + 8);
            float4 v3 = *(const float4*)(vr + 12);
            o[0]  += p * v0.x; o[1]  += p * v0.y; o[2]  += p * v0.z; o[3]  += p * v0.w;
            o[4]  += p * v1.x; o[5]  += p * v1.y; o[6]  += p * v1.z; o[7]  += p * v1.w;
            o[8]  += p * v2.x; o[9]  += p * v2.y; o[10] += p * v2.z; o[11] += p * v2.w;
            o[12] += p * v3.x; o[13] += p * v3.y; o[14] += p * v3.z; o[15] += p * v3.w;
        }
        __syncthreads();
    }

    float inv = 1.0f / l;
    size_t ooff = base + (size_t)gq * C_ + seg * 16;
    *(float4*)&O[ooff]      = make_float4(o[0] * inv,  o[1] * inv,  o[2] * inv,  o[3] * inv);
    *(float4*)&O[ooff + 4]  = make_float4(o[4] * inv,  o[5] * inv,  o[6] * inv,  o[7] * inv);
    *(float4*)&O[ooff + 8]  = make_float4(o[8] * inv,  o[9] * inv,  o[10] * inv, o[11] * inv);
    *(float4*)&O[ooff + 12] = make_float4(o[12] * inv, o[13] * inv, o[14] * inv, o[15] * inv);
}

// ---------------- loss ----------------
__global__ void loss_init_kernel(float* loss) { *loss = 0.f; }

__global__ __launch_bounds__(256) void loss_kernel(
    const float* __restrict__ logits, const int* __restrict__ targets,
    float* __restrict__ loss)
{
    __shared__ float red[8];
    __shared__ float bmx_s, bsum_s;
    int row = blockIdx.x, tid = threadIdx.x;
    const float4* lr4 = (const float4*)(logits + (size_t)row * V_);

    float mx = -1e30f;
    for (int i = tid; i < V_ / 4; i += 256) {
        float4 u = lr4[i];
        mx = fmaxf(mx, fmaxf(fmaxf(u.x, u.y), fmaxf(u.z, u.w)));
    }
    #pragma unroll
    for (int o = 16; o; o >>= 1) mx = fmaxf(mx, __shfl_xor_sync(0xffffffffu, mx, o));
    if ((tid & 31) == 0) red[tid >> 5] = mx;
    __syncthreads();
    if (tid == 0) {
        float t = red[0];
        #pragma unroll
        for (int i = 1; i < 8; i++) t = fmaxf(t, red[i]);
        bmx_s = t;
    }
    __syncthreads();
    float bmx = bmx_s;

    float s = 0.f;
    for (int i = tid; i < V_ / 4; i += 256) {
        float4 u = lr4[i];
        s += __expf(u.x - bmx) + __expf(u.y - bmx) + __expf(u.z - bmx) + __expf(u.w - bmx);
    }
    #pragma unroll
    for (int o = 16; o; o >>= 1) s += __shfl_xor_sync(0xffffffffu, s, o);
    if ((tid & 31) == 0) red[tid >> 5] = s;
    __syncthreads();
    if (tid == 0) {
        float t = 0.f;
        #pragma unroll
        for (int i = 0; i < 8; i++) t += red[i];
        bsum_s = t;
    }
    __syncthreads();
    if (tid == 0) {
        int tgt = targets[row];
        float lp = logits[(size_t)row * V_ + tgt] - bmx - logf(bsum_s);
        atomicAdd(loss, -lp * (1.0f / M_));
    }
}

// ---------------- host ----------------
extern "C" void kernel_launch(void* const* d_in, const int* in_sizes, int n_in,
                              void* d_out, int out_size)
{
    const int*   idx     = (const int*)d_in[0];
    const int*   targets = (const int*)d_in[1];
    const float* tok     = (const float*)d_in[2];
    const float* pos     = (const float*)d_in[3];
    const float* ln1g    = (const float*)d_in[4];
    const float* ln1b    = (const float*)d_in[5];
    const float* Wq      = (const float*)d_in[6];
    const float* Wk      = (const float*)d_in[7];
    const float* Wv      = (const float*)d_in[8];
    const float* Wo      = (const float*)d_in[9];
    const float* bo      = (const float*)d_in[10];
    const float* ln2g    = (const float*)d_in[11];
    const float* ln2b    = (const float*)d_in[12];
    const float* W1      = (const float*)d_in[13];
    const float* b1      = (const float*)d_in[14];
    const float* W2      = (const float*)d_in[15];
    const float* b2      = (const float*)d_in[16];
    const float* lnfg    = (const float*)d_in[17];
    const float* lnfb    = (const float*)d_in[18];
    const float* Wlm     = (const float*)d_in[19];
    const float* blm     = (const float*)d_in[20];

    static float *x = nullptr, *h = nullptr, *big = nullptr, *lgbuf = nullptr;
    static bool init = false;
    if (!init) {
        cudaGetSymbolAddress((void**)&x, g_x);
        cudaGetSymbolAddress((void**)&h, g_h);
        cudaGetSymbolAddress((void**)&big, g_big);
        cudaGetSymbolAddress((void**)&lgbuf, g_logits);
        cudaFuncSetAttribute(attn_kernel,
                             cudaFuncAttributeMaxDynamicSharedMemorySize, ATTN_SMEM);
        init = true;
    }

    const size_t NTV = (size_t)M_ * V_;
    float* logits_ptr = ((size_t)out_size >= NTV) ? (float*)d_out : lgbuf;
    float* loss_ptr = nullptr;
    if ((size_t)out_size == NTV + 1)     loss_ptr = (float*)d_out + NTV;
    else if ((size_t)out_size < NTV)     loss_ptr = (float*)d_out;  // loss-only output

    float* qb_  = big;
    float* kb_  = big + (size_t)M_ * C_;
    float* vb_  = big + (size_t)2 * M_ * C_;
    float* att_ = big + (size_t)3 * M_ * C_;
    float* mlp_ = big;  // reuses qkv+att space (dead by then)

    dim3 g1(C_ / 128, M_ / 128);       // N=1024
    dim3 g4(4 * C_ / 128, M_ / 128);   // N=4096
    dim3 gl(V_ / 128, M_ / 128);       // N=50304 (= 128*393)
    dim3 ga(T_ / 64, B_ * H_);

    embed_kernel<<<M_, 256>>>(idx, tok, pos, x);

    for (int l = 0; l < L_; l++) {
        const float* Wq_l = Wq + (size_t)l * C_ * C_;
        const float* Wk_l = Wk + (size_t)l * C_ * C_;
        const float* Wv_l = Wv + (size_t)l * C_ * C_;
        const float* Wo_l = Wo + (size_t)l * C_ * C_;
        const float* W1_l = W1 + (size_t)l * C_ * 4 * C_;
        const float* W2_l = W2 + (size_t)l * 4 * C_ * C_;

        ln_kernel<<<M_, 256>>>(x, ln1g + (size_t)l * C_, ln1b + (size_t)l * C_, h);
        sgemm_kernel<0, 0, 0><<<g1, 256>>>(h, Wq_l, nullptr, nullptr, qb_, M_, C_, C_);
        sgemm_kernel<0, 0, 0><<<g1, 256>>>(h, Wk_l, nullptr, nullptr, kb_, M_, C_, C_);
        sgemm_kernel<0, 0, 0><<<g1, 256>>>(h, Wv_l, nullptr, nullptr, vb_, M_, C_, C_);
        attn_kernel<<<ga, 256, ATTN_SMEM>>>(qb_, kb_, vb_, att_);
        sgemm_kernel<1, 0, 1><<<g1, 256>>>(att_, Wo_l, bo + (size_t)l * C_, x, x, M_, C_, C_);
        ln_kernel<<<M_, 256>>>(x, ln2g + (size_t)l * C_, ln2b + (size_t)l * C_, h);
        sgemm_kernel<1, 1, 0><<<g4, 256>>>(h, W1_l, b1 + (size_t)l * 4 * C_, nullptr, mlp_, M_, 4 * C_, C_);
        sgemm_kernel<1, 0, 1><<<g1, 256>>>(mlp_, W2_l, b2 + (size_t)l * C_, x, x, M_, C_, 4 * C_);
    }

    ln_kernel<<<M_, 256>>>(x, lnfg, lnfb, h);
    sgemm_kernel<1, 0, 0><<<gl, 256>>>(h, Wlm, blm, nullptr, logits_ptr, M_, V_, C_);

    if (loss_ptr) {
        loss_init_kernel<<<1, 1>>>(loss_ptr);
        loss_kernel<<<M_, 256>>>(logits_ptr, targets, loss_ptr);
    }
}

// round 3
// speedup vs baseline: 1.8280x; 1.8280x over previous
#include <cuda_runtime.h>
#include <cuda_bf16.h>
#include <math.h>
#include <stdint.h>

#define T_ 1024
#define C_ 1024
#define B_ 4
#define H_ 16
#define L_ 12
#define V_ 50304
#define M_ 4096   // B*T tokens

// ======================= scratch (device globals) =======================
__device__ float g_x[(size_t)M_ * C_];
__device__ float g_h[(size_t)M_ * C_];
__device__ float g_big[(size_t)M_ * 4 * C_];
__device__ float g_logits[(size_t)M_ * V_];
// bf16 split weights, transposed to [N,K]
__device__ __nv_bfloat16 g_qkvo_hi[(size_t)4 * L_ * C_ * C_];
__device__ __nv_bfloat16 g_qkvo_lo[(size_t)4 * L_ * C_ * C_];
__device__ __nv_bfloat16 g_w1_hi[(size_t)L_ * C_ * 4 * C_];
__device__ __nv_bfloat16 g_w1_lo[(size_t)L_ * C_ * 4 * C_];
__device__ __nv_bfloat16 g_w2_hi[(size_t)L_ * 4 * C_ * C_];
__device__ __nv_bfloat16 g_w2_lo[(size_t)L_ * 4 * C_ * C_];
__device__ __nv_bfloat16 g_wlm_hi[(size_t)V_ * C_];
__device__ __nv_bfloat16 g_wlm_lo[(size_t)V_ * C_];

// ======================= small asm helpers =======================
__device__ __forceinline__ uint32_t smem_u32(const void* p) {
    uint32_t a;
    asm("{ .reg .u64 t; cvta.to.shared.u64 t, %1; cvt.u32.u64 %0, t; }" : "=r"(a) : "l"(p));
    return a;
}
__device__ __forceinline__ void ldmatrix_x4(uint32_t* r, uint32_t addr) {
    asm volatile("ldmatrix.sync.aligned.m8n8.x4.shared.b16 {%0,%1,%2,%3}, [%4];"
        : "=r"(r[0]), "=r"(r[1]), "=r"(r[2]), "=r"(r[3]) : "r"(addr));
}
__device__ __forceinline__ void mma_bf16(float* d, const uint32_t* a, const uint32_t* b) {
    asm volatile(
        "mma.sync.aligned.m16n8k16.row.col.f32.bf16.bf16.f32 "
        "{%0,%1,%2,%3}, {%4,%5,%6,%7}, {%8,%9}, {%0,%1,%2,%3};"
        : "+f"(d[0]), "+f"(d[1]), "+f"(d[2]), "+f"(d[3])
        : "r"(a[0]), "r"(a[1]), "r"(a[2]), "r"(a[3]), "r"(b[0]), "r"(b[1]));
}
#define CP_ASYNC16(dst, src) \
    asm volatile("cp.async.cg.shared.global [%0], [%1], 16;" :: "r"(dst), "l"(src))
#define CP_COMMIT() asm volatile("cp.async.commit_group;")
#define CP_WAIT0()  asm volatile("cp.async.wait_group 0;")

// ======================= weight transpose + split =======================
// W [K,N] fp32 (per layer, blockIdx.z) -> hi/lo [N,K] bf16
__global__ __launch_bounds__(256) void wsplit_kernel(
    const float* __restrict__ W, __nv_bfloat16* __restrict__ hi,
    __nv_bfloat16* __restrict__ lo, int K, int N)
{
    __shared__ float t[32][33];
    size_t lsz = (size_t)K * N;
    const float* Wl = W + (size_t)blockIdx.z * lsz;
    __nv_bfloat16* hil = hi + (size_t)blockIdx.z * lsz;
    __nv_bfloat16* lol = lo + (size_t)blockIdx.z * lsz;
    int n0 = blockIdx.x * 32, k0 = blockIdx.y * 32;
    int tx = threadIdx.x & 31, ty = threadIdx.x >> 5;  // 32x8
    #pragma unroll
    for (int i = 0; i < 4; i++)
        t[ty + 8 * i][tx] = Wl[(size_t)(k0 + ty + 8 * i) * N + n0 + tx];
    __syncthreads();
    #pragma unroll
    for (int i = 0; i < 4; i++) {
        float v = t[tx][ty + 8 * i];
        __nv_bfloat16 h = __float2bfloat16(v);
        __nv_bfloat16 l = __float2bfloat16(v - __bfloat162float(h));
        size_t off = (size_t)(n0 + ty + 8 * i) * K + k0 + tx;
        hil[off] = h;
        lol[off] = l;
    }
}

// ======================= HMMA GEMM (mma.sync bf16 x3 compensation) =====
// C[M,N] = A[M,K](fp32) @ W[N,K]^T (bf16 hi/lo)  (+bias,+resid,relu)
// 128x128 tile, BK=32, 256 thr, 8 warps (4m x 2n), warp tile 32x64.
#define RSB 80                      // smem row stride bytes (32 bf16 + 8 pad)
#define STG (4 * 128 * RSB)         // one stage: Ah,Al,Bh,Bl = 40960 B
#define AH_OFF(s) ((s) * STG)
#define AL_OFF(s) (AH_OFF(s) + 128 * RSB)
#define BH_OFF(s) (AH_OFF(s) + 2 * 128 * RSB)
#define BL_OFF(s) (AH_OFF(s) + 3 * 128 * RSB)
#define GEMM_SMEM (2 * STG)         // 81920

template <int BIAS, int RELU, int RESID>
__global__ __launch_bounds__(256) void gemm_mma(
    const float* __restrict__ A, const __nv_bfloat16* __restrict__ Bhi,
    const __nv_bfloat16* __restrict__ Blo, const float* __restrict__ bias,
    const float* __restrict__ resid, float* __restrict__ C, int N, int K)
{
    extern __shared__ char sm[];
    uint32_t sb = smem_u32(sm);
    int tid = threadIdx.x;
    int lane = tid & 31, wid = tid >> 5;
    int warp_m = wid >> 1, warp_n = wid & 1;
    int m0 = blockIdx.x * 128, n0 = blockIdx.y * 128;
    const int NC = K >> 5;

    float acc[2][8][4];
    #pragma unroll
    for (int t = 0; t < 2; t++)
        #pragma unroll
        for (int n = 0; n < 8; n++)
            #pragma unroll
            for (int j = 0; j < 4; j++) acc[t][n][j] = 0.f;

    // ---- loaders ----
    float4 apf[4];
    const int a_row[1] = {0};
    (void)a_row;

    auto loadA = [&](int c) {
        int k0 = c << 5;
        #pragma unroll
        for (int j = 0; j < 4; j++) {
            int fi = tid + j * 256;
            int row = fi >> 3, col = (fi & 7) << 2;
            apf[j] = *(const float4*)(A + (size_t)(m0 + row) * K + k0 + col);
        }
    };
    auto storeA = [&](int s) {
        #pragma unroll
        for (int j = 0; j < 4; j++) {
            int fi = tid + j * 256;
            int row = fi >> 3, col = (fi & 7) << 2;
            float4 v = apf[j];
            __nv_bfloat16 h0 = __float2bfloat16(v.x);
            __nv_bfloat16 h1 = __float2bfloat16(v.y);
            __nv_bfloat16 h2 = __float2bfloat16(v.z);
            __nv_bfloat16 h3 = __float2bfloat16(v.w);
            __nv_bfloat16 l0 = __float2bfloat16(v.x - __bfloat162float(h0));
            __nv_bfloat16 l1 = __float2bfloat16(v.y - __bfloat162float(h1));
            __nv_bfloat16 l2 = __float2bfloat16(v.z - __bfloat162float(h2));
            __nv_bfloat16 l3 = __float2bfloat16(v.w - __bfloat162float(h3));
            uint2 uh = make_uint2(
                ((uint32_t)__bfloat16_as_ushort(h1) << 16) | __bfloat16_as_ushort(h0),
                ((uint32_t)__bfloat16_as_ushort(h3) << 16) | __bfloat16_as_ushort(h2));
            uint2 ul = make_uint2(
                ((uint32_t)__bfloat16_as_ushort(l1) << 16) | __bfloat16_as_ushort(l0),
                ((uint32_t)__bfloat16_as_ushort(l3) << 16) | __bfloat16_as_ushort(l2));
            int off = row * RSB + col * 2;
            *(uint2*)(sm + AH_OFF(s) + off) = uh;
            *(uint2*)(sm + AL_OFF(s) + off) = ul;
        }
    };
    auto issueB = [&](int c, int s) {
        int k0 = c << 5;
        #pragma unroll
        for (int v = 0; v < 2; v++) {
            const __nv_bfloat16* src = v ? Blo : Bhi;
            uint32_t dstb = sb + (v ? BL_OFF(s) : BH_OFF(s));
            #pragma unroll
            for (int j = 0; j < 2; j++) {
                int fi = tid + j * 256;
                int row = fi >> 2, c16 = (fi & 3) << 3;
                const void* g = src + (size_t)(n0 + row) * K + k0 + c16;
                CP_ASYNC16(dstb + row * RSB + c16 * 2, g);
            }
        }
        CP_COMMIT();
    };

    auto compute = [&](int s) {
        #pragma unroll
        for (int ks = 0; ks < 2; ks++) {
            uint32_t ah[2][4], al[2][4];
            #pragma unroll
            for (int t = 0; t < 2; t++) {
                int row = warp_m * 32 + t * 16 + (lane & 15);
                uint32_t off = row * RSB + ks * 32 + ((lane >> 4) << 4);
                ldmatrix_x4(ah[t], sb + AH_OFF(s) + off);
                ldmatrix_x4(al[t], sb + AL_OFF(s) + off);
            }
            uint32_t bh[8][2], bl[8][2];
            #pragma unroll
            for (int p = 0; p < 4; p++) {
                int row = warp_n * 64 + p * 16 + (lane & 7) + (((lane >> 4) & 1) << 3);
                uint32_t off = row * RSB + ks * 32 + (((lane >> 3) & 1) << 4);
                uint32_t r[4];
                ldmatrix_x4(r, sb + BH_OFF(s) + off);
                bh[2 * p][0] = r[0]; bh[2 * p][1] = r[1];
                bh[2 * p + 1][0] = r[2]; bh[2 * p + 1][1] = r[3];
                ldmatrix_x4(r, sb + BL_OFF(s) + off);
                bl[2 * p][0] = r[0]; bl[2 * p][1] = r[1];
                bl[2 * p + 1][0] = r[2]; bl[2 * p + 1][1] = r[3];
            }
            #pragma unroll
            for (int t = 0; t < 2; t++)
                #pragma unroll
                for (int n = 0; n < 8; n++) {
                    mma_bf16(acc[t][n], ah[t], bh[n]);
                    mma_bf16(acc[t][n], al[t], bh[n]);
                    mma_bf16(acc[t][n], ah[t], bl[n]);
                }
        }
    };

    // ---- pipeline ----
    loadA(0);
    issueB(0, 0);
    storeA(0);
    CP_WAIT0();
    __syncthreads();

    for (int c = 0; c < NC; c++) {
        int s = c & 1;
        bool pf = (c + 1 < NC);
        if (pf) { issueB(c + 1, s ^ 1); loadA(c + 1); }
        compute(s);
        if (pf) { storeA(s ^ 1); CP_WAIT0(); }
        __syncthreads();
    }

    // ---- epilogue ----
    #pragma unroll
    for (int t = 0; t < 2; t++) {
        int row0 = m0 + warp_m * 32 + t * 16 + (lane >> 2);
        #pragma unroll
        for (int n = 0; n < 8; n++) {
            int col = n0 + warp_n * 64 + n * 8 + (lane & 3) * 2;
            float b0 = 0.f, b1 = 0.f;
            if (BIAS) { b0 = bias[col]; b1 = bias[col + 1]; }
            float v0 = acc[t][n][0] + b0, v1 = acc[t][n][1] + b1;
            float v2 = acc[t][n][2] + b0, v3 = acc[t][n][3] + b1;
            size_t o0 = (size_t)row0 * N + col;
            size_t o1 = (size_t)(row0 + 8) * N + col;
            if (RESID) {
                float2 r0 = *(const float2*)(resid + o0);
                float2 r1 = *(const float2*)(resid + o1);
                v0 += r0.x; v1 += r0.y; v2 += r1.x; v3 += r1.y;
            }
            if (RELU) {
                v0 = fmaxf(v0, 0.f); v1 = fmaxf(v1, 0.f);
                v2 = fmaxf(v2, 0.f); v3 = fmaxf(v3, 0.f);
            }
            *(float2*)(C + o0) = make_float2(v0, v1);
            *(float2*)(C + o1) = make_float2(v2, v3);
        }
    }
}

// ======================= embedding ====================================
__global__ __launch_bounds__(256) void embed_kernel(
    const int* __restrict__ idx, const float* __restrict__ tok,
    const float* __restrict__ pos, float* __restrict__ x)
{
    int bt = blockIdx.x;
    int t = bt & (T_ - 1);
    int token = idx[bt];
    int c = threadIdx.x * 4;
    float4 tv = *(const float4*)(tok + (size_t)token * C_ + c);
    float4 pv = *(const float4*)(pos + (size_t)t * C_ + c);
    *(float4*)(x + (size_t)bt * C_ + c) =
        make_float4(tv.x + pv.x, tv.y + pv.y, tv.z + pv.z, tv.w + pv.w);
}

// ======================= layernorm ====================================
__global__ __launch_bounds__(256) void ln_kernel(
    const float* __restrict__ x, const float* __restrict__ g,
    const float* __restrict__ b, float* __restrict__ y)
{
    __shared__ float red[8];
    __shared__ float bc_mean, bc_inv;
    int row = blockIdx.x, tid = threadIdx.x;
    const float* xr = x + (size_t)row * C_;
    float4 xv = *(const float4*)(xr + tid * 4);
    float s = xv.x + xv.y + xv.z + xv.w;
    #pragma unroll
    for (int o = 16; o; o >>= 1) s += __shfl_xor_sync(0xffffffffu, s, o);
    if ((tid & 31) == 0) red[tid >> 5] = s;
    __syncthreads();
    if (tid == 0) {
        float t = 0.f;
        #pragma unroll
        for (int i = 0; i < 8; i++) t += red[i];
        bc_mean = t * (1.0f / C_);
    }
    __syncthreads();
    float mean = bc_mean;
    float d0 = xv.x - mean, d1 = xv.y - mean, d2 = xv.z - mean, d3 = xv.w - mean;
    float sq = d0 * d0 + d1 * d1 + d2 * d2 + d3 * d3;
    #pragma unroll
    for (int o = 16; o; o >>= 1) sq += __shfl_xor_sync(0xffffffffu, sq, o);
    if ((tid & 31) == 0) red[tid >> 5] = sq;
    __syncthreads();
    if (tid == 0) {
        float t = 0.f;
        #pragma unroll
        for (int i = 0; i < 8; i++) t += red[i];
        bc_inv = rsqrtf(t * (1.0f / C_) + 1e-5f);
    }
    __syncthreads();
    float inv = bc_inv;
    float4 gv = *(const float4*)(g + tid * 4);
    float4 bv = *(const float4*)(b + tid * 4);
    *(float4*)(y + (size_t)row * C_ + tid * 4) =
        make_float4(d0 * inv * gv.x + bv.x, d1 * inv * gv.y + bv.y,
                    d2 * inv * gv.z + bv.z, d3 * inv * gv.w + bv.w);
}

// ======================= causal flash attention =======================
#define ATTN_SMEM (4 * 64 * 68 * 4)
__global__ __launch_bounds__(256) void attn_kernel(
    const float* __restrict__ Q, const float* __restrict__ K,
    const float* __restrict__ V, float* __restrict__ O)
{
    extern __shared__ float smf[];
    float (*Qs)[68]  = (float(*)[68])smf;
    float (*KsT)[68] = (float(*)[68])(smf + 64 * 68);
    float (*Vs)[68]  = (float(*)[68])(smf + 2 * 64 * 68);
    float (*Ps)[68]  = (float(*)[68])(smf + 3 * 64 * 68);

    int qb = blockIdx.x;
    int bh = blockIdx.y;
    int b = bh >> 4, hh = bh & 15;
    size_t base = (size_t)b * T_ * C_ + (size_t)hh * 64;
    int tid = threadIdx.x;
    int row = tid >> 2, seg = tid & 3;
    int gq = qb * 64 + row;

    for (int i = tid; i < 64 * 16; i += 256) {
        int r = i >> 4, c4 = (i & 15) << 2;
        *(float4*)&Qs[r][c4] = *(const float4*)&Q[base + (size_t)(qb * 64 + r) * C_ + c4];
    }
    __syncthreads();

    float m = -1e30f, l = 0.f;
    float o[16];
    #pragma unroll
    for (int j = 0; j < 16; j++) o[j] = 0.f;

    for (int kb = 0; kb <= qb; kb++) {
        for (int i = tid; i < 64 * 16; i += 256) {
            int r = i >> 4, c4 = (i & 15) << 2;
            size_t goff = base + (size_t)(kb * 64 + r) * C_ + c4;
            float4 kv = *(const float4*)&K[goff];
            KsT[c4 + 0][r] = kv.x;
            KsT[c4 + 1][r] = kv.y;
            KsT[c4 + 2][r] = kv.z;
            KsT[c4 + 3][r] = kv.w;
            *(float4*)&Vs[r][c4] = *(const float4*)&V[goff];
        }
        __syncthreads();

        float sv[16];
        #pragma unroll
        for (int j = 0; j < 16; j++) sv[j] = 0.f;
        #pragma unroll 16
        for (int d = 0; d < 64; d++) {
            float qd = Qs[row][d];
            float4 k0 = *(const float4*)&KsT[d][seg * 16];
            float4 k1 = *(const float4*)&KsT[d][seg * 16 + 4];
            float4 k2 = *(const float4*)&KsT[d][seg * 16 + 8];
            float4 k3 = *(const float4*)&KsT[d][seg * 16 + 12];
            sv[0]  += qd * k0.x; sv[1]  += qd * k0.y; sv[2]  += qd * k0.z; sv[3]  += qd * k0.w;
            sv[4]  += qd * k1.x; sv[5]  += qd * k1.y; sv[6]  += qd * k1.z; sv[7]  += qd * k1.w;
            sv[8]  += qd * k2.x; sv[9]  += qd * k2.y; sv[10] += qd * k2.z; sv[11] += qd * k2.w;
            sv[12] += qd * k3.x; sv[13] += qd * k3.y; sv[14] += qd * k3.z; sv[15] += qd * k3.w;
        }
        #pragma unroll
        for (int j = 0; j < 16; j++) {
            int gk = kb * 64 + seg * 16 + j;
            sv[j] = (gk <= gq) ? sv[j] * 0.125f : -1e30f;
        }

        float tmax = sv[0];
        #pragma unroll
        for (int j = 1; j < 16; j++) tmax = fmaxf(tmax, sv[j]);
        tmax = fmaxf(tmax, __shfl_xor_sync(0xffffffffu, tmax, 1));
        tmax = fmaxf(tmax, __shfl_xor_sync(0xffffffffu, tmax, 2));
        float mnew = fmaxf(m, tmax);
        float corr = __expf(m - mnew);
        float ls = 0.f;
        #pragma unroll
        for (int j = 0; j < 16; j++) {
            float p = __expf(sv[j] - mnew);
            Ps[row][seg * 16 + j] = p;
            ls += p;
        }
        ls += __shfl_xor_sync(0xffffffffu, ls, 1);
        ls += __shfl_xor_sync(0xffffffffu, ls, 2);
        l = l * corr + ls;
        m = mnew;
        #pragma unroll
        for (int j = 0; j < 16; j++) o[j] *= corr;
        __syncwarp();

        #pragma unroll 8
        for (int kk = 0; kk < 64; kk++) {
            float p = Ps[row][kk];
            const float* vr = &Vs[kk][seg * 16];
            float4 v0 = *(const float4*)(vr);
            float4 v1 = *(const float4*)(vr + 4);
            float4 v2 = *(const float4*)(vr + 8);
            float4 v3 = *(const float4*)(vr + 12);
            o[0]  += p * v0.x; o[1]  += p * v0.y; o[2]  += p * v0.z; o[3]  += p * v0.w;
            o[4]  += p * v1.x; o[5]  += p * v1.y; o[6]  += p * v1.z; o[7]  += p * v1.w;
            o[8]  += p * v2.x; o[9]  += p * v2.y; o[10] += p * v2.z; o[11] += p * v2.w;
            o[12] += p * v3.x; o[13] += p * v3.y; o[14] += p * v3.z; o[15] += p * v3.w;
        }
        __syncthreads();
    }

    float inv = 1.0f / l;
    size_t ooff = base + (size_t)gq * C_ + seg * 16;
    *(float4*)&O[ooff]      = make_float4(o[0] * inv,  o[1] * inv,  o[2] * inv,  o[3] * inv);
    *(float4*)&O[ooff + 4]  = make_float4(o[4] * inv,  o[5] * inv,  o[6] * inv,  o[7] * inv);
    *(float4*)&O[ooff + 8]  = make_float4(o[8] * inv,  o[9] * inv,  o[10] * inv, o[11] * inv);
    *(float4*)&O[ooff + 12] = make_float4(o[12] * inv, o[13] * inv, o[14] * inv, o[15] * inv);
}

// ======================= loss =========================================
__global__ void loss_init_kernel(float* loss) { *loss = 0.f; }

__global__ __launch_bounds__(256) void loss_kernel(
    const float* __restrict__ logits, const int* __restrict__ targets,
    float* __restrict__ loss)
{
    __shared__ float red[8];
    __shared__ float bmx_s, bsum_s;
    int row = blockIdx.x, tid = threadIdx.x;
    const float4* lr4 = (const float4*)(logits + (size_t)row * V_);

    float mx = -1e30f;
    for (int i = tid; i < V_ / 4; i += 256) {
        float4 u = lr4[i];
        mx = fmaxf(mx, fmaxf(fmaxf(u.x, u.y), fmaxf(u.z, u.w)));
    }
    #pragma unroll
    for (int o = 16; o; o >>= 1) mx = fmaxf(mx, __shfl_xor_sync(0xffffffffu, mx, o));
    if ((tid & 31) == 0) red[tid >> 5] = mx;
    __syncthreads();
    if (tid == 0) {
        float t = red[0];
        #pragma unroll
        for (int i = 1; i < 8; i++) t = fmaxf(t, red[i]);
        bmx_s = t;
    }
    __syncthreads();
    float bmx = bmx_s;

    float s = 0.f;
    for (int i = tid; i < V_ / 4; i += 256) {
        float4 u = lr4[i];
        s += __expf(u.x - bmx) + __expf(u.y - bmx) + __expf(u.z - bmx) + __expf(u.w - bmx);
    }
    #pragma unroll
    for (int o = 16; o; o >>= 1) s += __shfl_xor_sync(0xffffffffu, s, o);
    if ((tid & 31) == 0) red[tid >> 5] = s;
    __syncthreads();
    if (tid == 0) {
        float t = 0.f;
        #pragma unroll
        for (int i = 0; i < 8; i++) t += red[i];
        bsum_s = t;
    }
    __syncthreads();
    if (tid == 0) {
        int tgt = targets[row];
        float lp = logits[(size_t)row * V_ + tgt] - bmx - logf(bsum_s);
        atomicAdd(loss, -lp * (1.0f / M_));
    }
}

// ======================= host =========================================
extern "C" void kernel_launch(void* const* d_in, const int* in_sizes, int n_in,
                              void* d_out, int out_size)
{
    const int*   idx     = (const int*)d_in[0];
    const int*   targets = (const int*)d_in[1];
    const float* tok     = (const float*)d_in[2];
    const float* pos     = (const float*)d_in[3];
    const float* ln1g    = (const float*)d_in[4];
    const float* ln1b    = (const float*)d_in[5];
    const float* Wq      = (const float*)d_in[6];
    const float* Wk      = (const float*)d_in[7];
    const float* Wv      = (const float*)d_in[8];
    const float* Wo      = (const float*)d_in[9];
    const float* bo      = (const float*)d_in[10];
    const float* ln2g    = (const float*)d_in[11];
    const float* ln2b    = (const float*)d_in[12];
    const float* W1      = (const float*)d_in[13];
    const float* b1      = (const float*)d_in[14];
    const float* W2      = (const float*)d_in[15];
    const float* b2      = (const float*)d_in[16];
    const float* lnfg    = (const float*)d_in[17];
    const float* lnfb    = (const float*)d_in[18];
    const float* Wlm     = (const float*)d_in[19];
    const float* blm     = (const float*)d_in[20];

    static float *x = nullptr, *h = nullptr, *big = nullptr, *lgbuf = nullptr;
    static __nv_bfloat16 *qkvo_hi, *qkvo_lo, *w1_hi, *w1_lo, *w2_hi, *w2_lo, *wlm_hi, *wlm_lo;
    static bool init = false;
    if (!init) {
        cudaGetSymbolAddress((void**)&x, g_x);
        cudaGetSymbolAddress((void**)&h, g_h);
        cudaGetSymbolAddress((void**)&big, g_big);
        cudaGetSymbolAddress((void**)&lgbuf, g_logits);
        cudaGetSymbolAddress((void**)&qkvo_hi, g_qkvo_hi);
        cudaGetSymbolAddress((void**)&qkvo_lo, g_qkvo_lo);
        cudaGetSymbolAddress((void**)&w1_hi, g_w1_hi);
        cudaGetSymbolAddress((void**)&w1_lo, g_w1_lo);
        cudaGetSymbolAddress((void**)&w2_hi, g_w2_hi);
        cudaGetSymbolAddress((void**)&w2_lo, g_w2_lo);
        cudaGetSymbolAddress((void**)&wlm_hi, g_wlm_hi);
        cudaGetSymbolAddress((void**)&wlm_lo, g_wlm_lo);
        cudaFuncSetAttribute(attn_kernel, cudaFuncAttributeMaxDynamicSharedMemorySize, ATTN_SMEM);
        cudaFuncSetAttribute(gemm_mma<0,0,0>, cudaFuncAttributeMaxDynamicSharedMemorySize, GEMM_SMEM);
        cudaFuncSetAttribute(gemm_mma<1,0,1>, cudaFuncAttributeMaxDynamicSharedMemorySize, GEMM_SMEM);
        cudaFuncSetAttribute(gemm_mma<1,1,0>, cudaFuncAttributeMaxDynamicSharedMemorySize, GEMM_SMEM);
        cudaFuncSetAttribute(gemm_mma<1,0,0>, cudaFuncAttributeMaxDynamicSharedMemorySize, GEMM_SMEM);
        init = true;
    }

    const size_t NTV = (size_t)M_ * V_;
    float* logits_ptr = ((size_t)out_size >= NTV) ? (float*)d_out : lgbuf;
    float* loss_ptr = nullptr;
    if ((size_t)out_size == NTV + 1)     loss_ptr = (float*)d_out + NTV;
    else if ((size_t)out_size < NTV)     loss_ptr = (float*)d_out;

    float* qb_  = big;
    float* kb_  = big + (size_t)M_ * C_;
    float* vb_  = big + (size_t)2 * M_ * C_;
    float* att_ = big + (size_t)3 * M_ * C_;
    float* mlp_ = big;

    const size_t CC = (size_t)C_ * C_;
    const size_t LCC = (size_t)L_ * CC;

    // ---- weight prep (transpose + bf16 split) ----
    wsplit_kernel<<<dim3(C_ / 32, C_ / 32, L_), 256>>>(Wq, qkvo_hi + 0 * LCC, qkvo_lo + 0 * LCC, C_, C_);
    wsplit_kernel<<<dim3(C_ / 32, C_ / 32, L_), 256>>>(Wk, qkvo_hi + 1 * LCC, qkvo_lo + 1 * LCC, C_, C_);
    wsplit_kernel<<<dim3(C_ / 32, C_ / 32, L_), 256>>>(Wv, qkvo_hi + 2 * LCC, qkvo_lo + 2 * LCC, C_, C_);
    wsplit_kernel<<<dim3(C_ / 32, C_ / 32, L_), 256>>>(Wo, qkvo_hi + 3 * LCC, qkvo_lo + 3 * LCC, C_, C_);
    wsplit_kernel<<<dim3(4 * C_ / 32, C_ / 32, L_), 256>>>(W1, w1_hi, w1_lo, C_, 4 * C_);
    wsplit_kernel<<<dim3(C_ / 32, 4 * C_ / 32, L_), 256>>>(W2, w2_hi, w2_lo, 4 * C_, C_);
    wsplit_kernel<<<dim3(V_ / 32, C_ / 32, 1), 256>>>(Wlm, wlm_hi, wlm_lo, C_, V_);

    dim3 g1(M_ / 128, C_ / 128);
    dim3 g4(M_ / 128, 4 * C_ / 128);
    dim3 gl(M_ / 128, V_ / 128);
    dim3 ga(T_ / 64, B_ * H_);

    embed_kernel<<<M_, 256>>>(idx, tok, pos, x);

    for (int l = 0; l < L_; l++) {
        size_t wo = (size_t)l * CC;
        size_t w1o = (size_t)l * CC * 4;
        ln_kernel<<<M_, 256>>>(x, ln1g + (size_t)l * C_, ln1b + (size_t)l * C_, h);
        gemm_mma<0,0,0><<<g1, 256, GEMM_SMEM>>>(h, qkvo_hi + 0 * LCC + wo, qkvo_lo + 0 * LCC + wo, nullptr, nullptr, qb_, C_, C_);
        gemm_mma<0,0,0><<<g1, 256, GEMM_SMEM>>>(h, qkvo_hi + 1 * LCC + wo, qkvo_lo + 1 * LCC + wo, nullptr, nullptr, kb_, C_, C_);
        gemm_mma<0,0,0><<<g1, 256, GEMM_SMEM>>>(h, qkvo_hi + 2 * LCC + wo, qkvo_lo + 2 * LCC + wo, nullptr, nullptr, vb_, C_, C_);
        attn_kernel<<<ga, 256, ATTN_SMEM>>>(qb_, kb_, vb_, att_);
        gemm_mma<1,0,1><<<g1, 256, GEMM_SMEM>>>(att_, qkvo_hi + 3 * LCC + wo, qkvo_lo + 3 * LCC + wo, bo + (size_t)l * C_, x, x, C_, C_);
        ln_kernel<<<M_, 256>>>(x, ln2g + (size_t)l * C_, ln2b + (size_t)l * C_, h);
        gemm_mma<1,1,0><<<g4, 256, GEMM_SMEM>>>(h, w1_hi + w1o, w1_lo + w1o, b1 + (size_t)l * 4 * C_, nullptr, mlp_, 4 * C_, C_);
        gemm_mma<1,0,1><<<g1, 256, GEMM_SMEM>>>(mlp_, w2_hi + w1o, w2_lo + w1o, b2 + (size_t)l * C_, x, x, C_, 4 * C_);
    }

    ln_kernel<<<M_, 256>>>(x, lnfg, lnfb, h);
    gemm_mma<1,0,0><<<gl, 256, GEMM_SMEM>>>(h, wlm_hi, wlm_lo, blm, nullptr, logits_ptr, V_, C_);

    if (loss_ptr) {
        loss_init_kernel<<<1, 1>>>(loss_ptr);
        loss_kernel<<<M_, 256>>>(logits_ptr, targets, loss_ptr);
    }
}